// round 16
// baseline (speedup 1.0000x reference)
#include <cuda_runtime.h>
#include <cuda_bf16.h>
#include <math.h>
#include <stdint.h>

// Problem constants
#define NN 10000
#define EE 160000
#define LL 4
#define F_ATOM 92
#define BINS 80
#define EMB 64
#define HH 256
#define FINAL 10000
#define KP96 96

// ======================= scratch (device globals) ============================
__device__ float g_x  [(size_t)NN * HH];
__device__ float g_hsd[(size_t)NN * 1024];      // [N, hs|hd]
__device__ float g_t1 [(size_t)EE * EMB];
__device__ float g_y  [(size_t)EE * HH];
__device__ float g_m  [(size_t)EE * 2 * HH];
__device__ float g_h  [(size_t)NN * HH];
__device__ float g_sum[1024];                   // zero-init; finalize re-zeroes
__device__ float g_sq [1024];
__device__ float g_scale[512];
__device__ float g_shift[512];
__device__ float g_bias2[1024];
// CSR for dst-gather
__device__ int g_deg[NN];
__device__ int g_off[NN + 1];
__device__ int g_cur[NN];
__device__ int g_adj[EE];
// bf16 hi/lo split buffers
__device__ __nv_bfloat16 g_athi[(size_t)NN * KP96];
__device__ __nv_bfloat16 g_atlo[(size_t)NN * KP96];
__device__ __nv_bfloat16 g_rbfhi[(size_t)EE * KP96];
__device__ __nv_bfloat16 g_rbflo[(size_t)EE * KP96];
__device__ __nv_bfloat16 g_xhi [(size_t)NN * HH];
__device__ __nv_bfloat16 g_xlo [(size_t)NN * HH];
__device__ __nv_bfloat16 g_t1hi[(size_t)EE * EMB];
__device__ __nv_bfloat16 g_t1lo[(size_t)EE * EMB];
__device__ __nv_bfloat16 g_yhi [(size_t)EE * HH];
__device__ __nv_bfloat16 g_ylo [(size_t)EE * HH];
__device__ __nv_bfloat16 g_f1hi[(size_t)NN * 4 * HH];
__device__ __nv_bfloat16 g_f1lo[(size_t)NN * 4 * HH];
__device__ __nv_bfloat16 g_f2hi[(size_t)NN * 8 * HH];
__device__ __nv_bfloat16 g_f2lo[(size_t)NN * 8 * HH];
__device__ __nv_bfloat16 g_wthi[(size_t)FINAL * 2048];
__device__ __nv_bfloat16 g_wtlo[(size_t)FINAL * 2048];

// ======================= math helpers ========================================
__device__ __forceinline__ float softplusf(float x) {
    return fmaxf(x, 0.f) + log1pf(expf(-fabsf(x)));
}
__device__ __forceinline__ float sigmoidf(float x) {
    return 1.f / (1.f + expf(-x));
}

// ======================= mma.sync helpers ====================================
#define LDMATRIX_X4(R, addr) \
    asm volatile("ldmatrix.sync.aligned.m8n8.x4.shared.b16 {%0,%1,%2,%3}, [%4];" \
        : "=r"((R)[0]), "=r"((R)[1]), "=r"((R)[2]), "=r"((R)[3]) : "r"(addr))

#define MMA_BF16(d, a, b0, b1) \
    asm volatile("mma.sync.aligned.m16n8k16.row.col.f32.bf16.bf16.f32 " \
        "{%0,%1,%2,%3}, {%4,%5,%6,%7}, {%8,%9}, {%0,%1,%2,%3};" \
        : "+f"((d)[0]), "+f"((d)[1]), "+f"((d)[2]), "+f"((d)[3]) \
        : "r"((a)[0]), "r"((a)[1]), "r"((a)[2]), "r"((a)[3]), "r"(b0), "r"(b1))

#define CP_ASYNC_16(dst, src, sz) \
    asm volatile("cp.async.cg.shared.global [%0], [%1], 16, %2;" \
        :: "r"(dst), "l"(src), "r"(sz))
#define CP_ASYNC_COMMIT() asm volatile("cp.async.commit_group;" ::: "memory")
#define CP_ASYNC_WAIT0()  asm volatile("cp.async.wait_group 0;" ::: "memory")
#define CP_ASYNC_WAIT1()  asm volatile("cp.async.wait_group 1;" ::: "memory")

// ======================= tensor-core GEMM (mma.sync bf16 split) ==============
// C[M,N2] = (Ahi+Alo)[M,K] x ((Bhi+Blo)[N2,K])^T + bias  (Ah*Bh+Ah*Bl+Al*Bh)
// Template-fused options:
//   GATHER: + ghs[gsrc[row]*gstride] + ghd[gdst[row]*gstride]
//   STATS:  column sum/sumsq atomics (BN batch stats)
// CTA tile 128x128, K-chunk 32, 2-stage buffer with EARLY-ISSUE + wait_group 1
// (next chunk's loads enter the pipe before waiting on the current chunk).
// 1-D swizzled raster: groups of RASTER_G M-tiles iterate N fastest.

#define PITCHB 80             // bytes per smem row (40 bf16) -> conflict-free
#define TILE_BYTES (128 * PITCHB)          // 10240
#define OFF_AH 0
#define OFF_AL (TILE_BYTES)
#define OFF_BH (2 * TILE_BYTES)
#define OFF_BL (3 * TILE_BYTES)
#define STAGE_BYTES (4 * TILE_BYTES)       // 40960
#define SMEM_TOTAL_TC (2 * STAGE_BYTES)    // 81920
#define RASTER_G 16

template<bool GATHER, bool STATS>
__global__ __launch_bounds__(256) void gemm_tc(
    const __nv_bfloat16* __restrict__ Ahi, const __nv_bfloat16* __restrict__ Alo,
    const __nv_bfloat16* __restrict__ Bhi, const __nv_bfloat16* __restrict__ Blo,
    const float* __restrict__ bias,
    float* __restrict__ C,
    __nv_bfloat16* __restrict__ Chi, __nv_bfloat16* __restrict__ Clo,
    int M, int N2, int K, int relu,
    const int* __restrict__ gsrc, const int* __restrict__ gdst,
    const float* __restrict__ ghs, const float* __restrict__ ghd, int gstride,
    float* __restrict__ statSum, float* __restrict__ statSq)
{
    extern __shared__ char sm[];
    const uint32_t sb = (uint32_t)__cvta_generic_to_shared(sm);
    const int tid  = threadIdx.x;
    const int lane = tid & 31;
    const int wid  = tid >> 5;
    const int warp_m = wid & 1;
    const int warp_n = wid >> 1;

    // 1-D swizzled raster (pure indexing; bijective also when Mt % G != 0)
    const int Mt = (M + 127) >> 7;
    const int Nt = (N2 + 127) >> 7;
    const int pid = blockIdx.x;
    const int nig = RASTER_G * Nt;
    const int group_id = pid / nig;
    const int first_m = group_id * RASTER_G;
    int gsz = Mt - first_m; if (gsz > RASTER_G) gsz = RASTER_G;
    const int rem = pid % nig;
    const int m0 = (first_m + rem % gsz) << 7;
    const int n0 = (rem / gsz) << 7;

    float acc[4][4][4];
    #pragma unroll
    for (int i = 0; i < 4; i++)
        #pragma unroll
        for (int j = 0; j < 4; j++)
            #pragma unroll
            for (int k = 0; k < 4; k++) acc[i][j][k] = 0.f;

    const int nch = K >> 5;
    const int r0_ = tid >> 2;
    const int r1_ = (tid + 256) >> 2;
    const int c0_ = (tid & 3) * 16;

    auto issue_chunk = [&](int ch) {
        const long long kb = (long long)ch << 5;
        const uint32_t sbase = sb + (ch & 1) * STAGE_BYTES;
        #pragma unroll
        for (int half = 0; half < 2; half++) {
            const int row = half ? r1_ : r0_;
            const int cb = c0_;
            {
                int gr = m0 + row;
                int ok = (gr < M) ? 16 : 0;
                long long go = ((long long)gr * K + kb) * 2 + cb;
                CP_ASYNC_16(sbase + OFF_AH + row * PITCHB + cb, (const char*)Ahi + go, ok);
                CP_ASYNC_16(sbase + OFF_AL + row * PITCHB + cb, (const char*)Alo + go, ok);
            }
            {
                int gr = n0 + row;
                int ok = (gr < N2) ? 16 : 0;
                long long go = ((long long)gr * K + kb) * 2 + cb;
                CP_ASYNC_16(sbase + OFF_BH + row * PITCHB + cb, (const char*)Bhi + go, ok);
                CP_ASYNC_16(sbase + OFF_BL + row * PITCHB + cb, (const char*)Blo + go, ok);
            }
        }
        CP_ASYNC_COMMIT();
    };

    const int a_row = warp_m * 64 + (lane & 15);
    const int a_col = (lane >> 4) << 3;
    const int b_row = warp_n * 32 + ((lane >> 4) << 3) + (lane & 7);
    const int b_col = (lane >> 3 & 1) << 3;

    issue_chunk(0);

    for (int ch = 0; ch < nch; ch++) {
        // early-issue: next chunk's loads enter the pipe BEFORE waiting on
        // this chunk (buffer safety: trailing __syncthreads of prev iter).
        if (ch + 1 < nch) {
            issue_chunk(ch + 1);
            CP_ASYNC_WAIT1();
        } else {
            CP_ASYNC_WAIT0();
        }
        __syncthreads();

        const uint32_t sbase = sb + (ch & 1) * STAGE_BYTES;
        #pragma unroll
        for (int ks = 0; ks < 32; ks += 16) {
            uint32_t af[4][4], bh[2][4], bl[2][4];
            #pragma unroll
            for (int mt = 0; mt < 4; mt++)
                LDMATRIX_X4(af[mt], sbase + OFF_AH + (a_row + mt * 16) * PITCHB + (a_col + ks) * 2);
            #pragma unroll
            for (int pp = 0; pp < 2; pp++)
                LDMATRIX_X4(bh[pp], sbase + OFF_BH + (b_row + pp * 16) * PITCHB + (b_col + ks) * 2);
            #pragma unroll
            for (int mt = 0; mt < 4; mt++)
                #pragma unroll
                for (int nt = 0; nt < 4; nt++)
                    MMA_BF16(acc[mt][nt], af[mt],
                             bh[nt >> 1][(nt & 1) * 2], bh[nt >> 1][(nt & 1) * 2 + 1]);
            #pragma unroll
            for (int pp = 0; pp < 2; pp++)
                LDMATRIX_X4(bl[pp], sbase + OFF_BL + (b_row + pp * 16) * PITCHB + (b_col + ks) * 2);
            #pragma unroll
            for (int mt = 0; mt < 4; mt++)
                #pragma unroll
                for (int nt = 0; nt < 4; nt++)
                    MMA_BF16(acc[mt][nt], af[mt],
                             bl[nt >> 1][(nt & 1) * 2], bl[nt >> 1][(nt & 1) * 2 + 1]);
            #pragma unroll
            for (int mt = 0; mt < 4; mt++)
                LDMATRIX_X4(af[mt], sbase + OFF_AL + (a_row + mt * 16) * PITCHB + (a_col + ks) * 2);
            #pragma unroll
            for (int mt = 0; mt < 4; mt++)
                #pragma unroll
                for (int nt = 0; nt < 4; nt++)
                    MMA_BF16(acc[mt][nt], af[mt],
                             bh[nt >> 1][(nt & 1) * 2], bh[nt >> 1][(nt & 1) * 2 + 1]);
        }
        __syncthreads();
    }

    // epilogue
    const int er = m0 + warp_m * 64 + (lane >> 2);
    const int ec = n0 + warp_n * 32 + (lane & 3) * 2;

    float bvals[8];
    #pragma unroll
    for (int nt = 0; nt < 4; nt++)
        #pragma unroll
        for (int d = 0; d < 2; d++) {
            int gc = ec + nt * 8 + d;
            bvals[nt * 2 + d] = (gc < N2) ? bias[gc] : 0.f;
        }

    float csum[8], csq[8];
    if (STATS) {
        #pragma unroll
        for (int j = 0; j < 8; j++) { csum[j] = 0.f; csq[j] = 0.f; }
    }

    #pragma unroll
    for (int mt = 0; mt < 4; mt++) {
        #pragma unroll
        for (int half = 0; half < 2; half++) {
            int gr = er + mt * 16 + half * 8;
            if (gr >= M) continue;
            long long rb = (long long)gr * N2;
            const float* hsrow = nullptr;
            const float* hdrow = nullptr;
            if (GATHER) {
                hsrow = ghs + (long long)gsrc[gr] * gstride;
                hdrow = ghd + (long long)gdst[gr] * gstride;
            }
            #pragma unroll
            for (int nt = 0; nt < 4; nt++) {
                #pragma unroll
                for (int d = 0; d < 2; d++) {
                    int gc = ec + nt * 8 + d;
                    if (gc >= N2) continue;
                    float v = acc[mt][nt][half * 2 + d] + bvals[nt * 2 + d];
                    if (GATHER) v += hsrow[gc] + hdrow[gc];
                    if (relu) v = fmaxf(v, 0.f);
                    if (C) C[rb + gc] = v;
                    if (Chi) {
                        __nv_bfloat16 hb = __float2bfloat16(v);
                        Chi[rb + gc] = hb;
                        Clo[rb + gc] = __float2bfloat16(v - __bfloat162float(hb));
                    }
                    if (STATS) {
                        csum[nt * 2 + d] += v;
                        csq[nt * 2 + d]  += v * v;
                    }
                }
            }
        }
    }

    if (STATS) {
        #pragma unroll
        for (int j = 0; j < 8; j++) {
            float s = csum[j], q = csq[j];
            s += __shfl_xor_sync(0xFFFFFFFFu, s, 4);
            q += __shfl_xor_sync(0xFFFFFFFFu, q, 4);
            s += __shfl_xor_sync(0xFFFFFFFFu, s, 8);
            q += __shfl_xor_sync(0xFFFFFFFFu, q, 8);
            s += __shfl_xor_sync(0xFFFFFFFFu, s, 16);
            q += __shfl_xor_sync(0xFFFFFFFFu, q, 16);
            if (lane < 4) {
                int gc = n0 + warp_n * 32 + (j >> 1) * 8 + lane * 2 + (j & 1);
                if (gc < N2) {
                    atomicAdd(&statSum[gc], s);
                    atomicAdd(&statSq[gc], q);
                }
            }
        }
    }
}

// ======================= conversion kernels ==================================
__global__ void transpose_split(const float* __restrict__ W,
                                __nv_bfloat16* __restrict__ hi,
                                __nv_bfloat16* __restrict__ lo,
                                int K, int N, int Kpad) {
    __shared__ float tile[32][33];
    int kb = blockIdx.y * 32, nb = blockIdx.x * 32;
    #pragma unroll
    for (int i = 0; i < 32; i += 8) {
        int kk = kb + threadIdx.y + i;
        int nn = nb + threadIdx.x;
        tile[threadIdx.y + i][threadIdx.x] =
            (kk < K && nn < N) ? W[(long long)kk * N + nn] : 0.f;
    }
    __syncthreads();
    #pragma unroll
    for (int i = 0; i < 32; i += 8) {
        int nn = nb + threadIdx.y + i;
        int kk = kb + threadIdx.x;
        if (nn < N && kk < Kpad) {
            float v = tile[threadIdx.x][threadIdx.y + i];
            __nv_bfloat16 h = __float2bfloat16(v);
            hi[(long long)nn * Kpad + kk] = h;
            lo[(long long)nn * Kpad + kk] = __float2bfloat16(v - __bfloat162float(h));
        }
    }
}

__global__ void pad_split(const float* __restrict__ in,
                          __nv_bfloat16* __restrict__ hi,
                          __nv_bfloat16* __restrict__ lo,
                          long long rows, int Ks, int Kp) {
    long long i = (long long)blockIdx.x * blockDim.x + threadIdx.x;
    if (i >= rows * Kp) return;
    long long r = i / Kp;
    int c = (int)(i % Kp);
    float v = (c < Ks) ? in[r * Ks + c] : 0.f;
    __nv_bfloat16 h = __float2bfloat16(v);
    hi[i] = h;
    lo[i] = __float2bfloat16(v - __bfloat162float(h));
}

// ======================= CSR build kernels ===================================
__global__ void zero_int(int* __restrict__ p, int n) {
    int i = blockIdx.x * blockDim.x + threadIdx.x;
    if (i < n) p[i] = 0;
}

__global__ void deg_count(const int* __restrict__ dst, int* __restrict__ deg) {
    int e = blockIdx.x * blockDim.x + threadIdx.x;
    if (e < EE) atomicAdd(&deg[dst[e]], 1);
}

// single block of 1024 threads, each handles 10 consecutive nodes
__global__ void scan_offsets(const int* __restrict__ deg, int* __restrict__ off) {
    __shared__ int s[1024];
    int t = threadIdx.x;
    int base = t * 10;
    int loc[10];
    int sum = 0;
    #pragma unroll
    for (int i = 0; i < 10; i++) {
        int idx = base + i;
        int v = (idx < NN) ? deg[idx] : 0;
        loc[i] = sum;
        sum += v;
    }
    s[t] = sum;
    __syncthreads();
    for (int d = 1; d < 1024; d <<= 1) {
        int v = (t >= d) ? s[t - d] : 0;
        __syncthreads();
        s[t] += v;
        __syncthreads();
    }
    int excl = (t == 0) ? 0 : s[t - 1];
    #pragma unroll
    for (int i = 0; i < 10; i++) {
        int idx = base + i;
        if (idx < NN) off[idx] = excl + loc[i];
    }
    if (t == 1023) off[NN] = s[1023];
}

__global__ void fill_adj(const int* __restrict__ dst, const int* __restrict__ off,
                         int* __restrict__ cur, int* __restrict__ adj) {
    int e = blockIdx.x * blockDim.x + threadIdx.x;
    if (e >= EE) return;
    int n = dst[e];
    int p = atomicAdd(&cur[n], 1);
    adj[off[n] + p] = e;
}

// ======================= elementwise / stats kernels =========================
__global__ void concat_bias(const float* __restrict__ a, const float* __restrict__ b,
                            float* __restrict__ o) {
    int i = blockIdx.x * blockDim.x + threadIdx.x;
    if (i < 512) o[i] = a[i];
    else if (i < 1024) o[i] = b[i - 512];
}

__global__ void rbf_split(const float* __restrict__ r,
                          __nv_bfloat16* __restrict__ hi,
                          __nv_bfloat16* __restrict__ lo,
                          long long n) {
    long long i = (long long)blockIdx.x * blockDim.x + threadIdx.x;
    if (i >= n) return;
    int e = (int)(i / KP96);
    int b = (int)(i % KP96);
    float v = 0.f;
    if (b < BINS) {
        float rx = r[e * 3 + 0], ry = r[e * 3 + 1], rz = r[e * 3 + 2];
        float d = sqrtf(rx * rx + ry * ry + rz * rz);
        float ctr = (8.0f / 79.0f) * (float)b;
        float t = d - ctr;
        v = expf(-9.875f * t * t);
    }
    __nv_bfloat16 h = __float2bfloat16(v);
    hi[i] = h;
    lo[i] = __float2bfloat16(v - __bfloat162float(h));
}

__global__ void col_stats(const float* __restrict__ X, long long total, int N,
                          float* __restrict__ sum, float* __restrict__ sq) {
    __shared__ float ssum[512];
    __shared__ float ssq[512];
    for (int c = threadIdx.x; c < N; c += blockDim.x) { ssum[c] = 0.f; ssq[c] = 0.f; }
    __syncthreads();
    long long stride = (long long)gridDim.x * blockDim.x;
    for (long long i = (long long)blockIdx.x * blockDim.x + threadIdx.x;
         i < total; i += stride) {
        float v = X[i];
        int c = (int)(i % N);
        atomicAdd(&ssum[c], v);
        atomicAdd(&ssq[c], v * v);
    }
    __syncthreads();
    for (int c = threadIdx.x; c < N; c += blockDim.x) {
        atomicAdd(&sum[c], ssum[c]);
        atomicAdd(&sq[c], ssq[c]);
    }
}

// computes scale/shift AND re-zeroes sum/sq for the next use
__global__ void finalize_stats(float* __restrict__ sum, float* __restrict__ sq,
                               const float* __restrict__ gamma, const float* __restrict__ beta,
                               float* __restrict__ scale, float* __restrict__ shift,
                               int N, float invM) {
    int c = blockIdx.x * blockDim.x + threadIdx.x;
    if (c >= N) return;
    float mean = sum[c] * invM;
    float var  = sq[c] * invM - mean * mean;
    float inv  = rsqrtf(var + 1e-5f);
    float s    = gamma[c] * inv;
    scale[c] = s;
    shift[c] = beta[c] - mean * s;
    sum[c] = 0.f;
    sq[c]  = 0.f;
}

__global__ void bn_relu_split(float* __restrict__ X, long long n, int N,
                              const float* __restrict__ scale,
                              const float* __restrict__ shift,
                              __nv_bfloat16* __restrict__ hi,
                              __nv_bfloat16* __restrict__ lo,
                              int writeback) {
    long long i = (long long)blockIdx.x * blockDim.x + threadIdx.x;
    if (i >= n) return;
    int c = (int)(i % N);
    float v = fmaxf(fmaf(X[i], scale[c], shift[c]), 0.f);
    if (writeback) X[i] = v;
    __nv_bfloat16 h = __float2bfloat16(v);
    hi[i] = h;
    lo[i] = __float2bfloat16(v - __bfloat162float(h));
}

// CSR gather: block = node, thread = channel. No atomics, h written once.
__global__ __launch_bounds__(256) void gate_gather(
    const float* __restrict__ m,
    const float* __restrict__ scale, const float* __restrict__ shift,
    const int* __restrict__ off, const int* __restrict__ adj,
    float* __restrict__ h)
{
    int n = blockIdx.x;
    int c = threadIdx.x;
    float sa = scale[c], fa = shift[c];
    float sb = scale[256 + c], fb = shift[256 + c];
    float acc = 0.f;
    int i0 = off[n], i1 = off[n + 1];
    for (int i = i0; i < i1; i++) {
        int e = adj[i];
        long long base = (long long)e * 512;
        float a = fmaf(m[base + c],       sa, fa);
        float b = fmaf(m[base + 256 + c], sb, fb);
        acc += sigmoidf(a) * softplusf(b);
    }
    h[(long long)n * 256 + c] = acc;
}

__global__ void node_update(float* __restrict__ x, const float* __restrict__ h,
                            const float* __restrict__ scale, const float* __restrict__ shift,
                            __nv_bfloat16* __restrict__ xhi, __nv_bfloat16* __restrict__ xlo,
                            long long n) {
    long long i = (long long)blockIdx.x * blockDim.x + threadIdx.x;
    if (i >= n) return;
    int c = (int)(i & 255);
    float hb = fmaf(h[i], scale[c], shift[c]);
    float v = softplusf(x[i] + hb);
    x[i] = v;
    __nv_bfloat16 hh = __float2bfloat16(v);
    xhi[i] = hh;
    xlo[i] = __float2bfloat16(v - __bfloat162float(hh));
}

// ======================= host orchestration ==================================
template<bool GATHER, bool STATS>
static inline void launch_gemm(const __nv_bfloat16* Ahi, const __nv_bfloat16* Alo,
                               const __nv_bfloat16* Bhi, const __nv_bfloat16* Blo,
                               const float* bias, float* C,
                               __nv_bfloat16* Chi, __nv_bfloat16* Clo,
                               int M, int N, int K, int relu,
                               const int* gsrc = nullptr, const int* gdst = nullptr,
                               const float* ghs = nullptr, const float* ghd = nullptr,
                               int gstride = 0,
                               float* ssum = nullptr, float* ssq = nullptr) {
    int Mt = (M + 127) / 128, Nt = (N + 127) / 128;
    gemm_tc<GATHER, STATS><<<Mt * Nt, 256, SMEM_TOTAL_TC>>>(
        Ahi, Alo, Bhi, Blo, bias, C, Chi, Clo, M, N, K, relu,
        gsrc, gdst, ghs, ghd, gstride, ssum, ssq);
}

static inline void launch_transpose_split(const float* W, __nv_bfloat16* hi,
                                          __nv_bfloat16* lo, int K, int N, int Kpad) {
    dim3 grid((N + 31) / 32, (Kpad + 31) / 32);
    transpose_split<<<grid, dim3(32, 8)>>>(W, hi, lo, K, N, Kpad);
}

extern "C" void kernel_launch(void* const* d_in, const int* in_sizes, int n_in,
                              void* d_out, int out_size) {
    const float* atom = (const float*)d_in[0];
    const float* r    = (const float*)d_in[1];
    const int*   src  = (const int*)d_in[2];
    const int*   dst  = (const int*)d_in[3];
    const float* aW = (const float*)d_in[4];
    const float* ab = (const float*)d_in[5];
    const float* ag = (const float*)d_in[6];
    const float* abeta = (const float*)d_in[7];
    const float* e1W = (const float*)d_in[8];
    const float* e1b = (const float*)d_in[9];
    const float* e1g = (const float*)d_in[10];
    const float* e1beta = (const float*)d_in[11];
    const float* e2W = (const float*)d_in[12];
    const float* e2b = (const float*)d_in[13];
    const float* e2g = (const float*)d_in[14];
    const float* e2beta = (const float*)d_in[15];
    const float* cWs = (const float*)d_in[16];
    const float* cbs = (const float*)d_in[17];
    const float* cWd = (const float*)d_in[18];
    const float* cbd = (const float*)d_in[19];
    const float* cWe = (const float*)d_in[20];
    const float* cbe = (const float*)d_in[21];
    const float* cmg = (const float*)d_in[22];
    const float* cmb = (const float*)d_in[23];
    const float* cng = (const float*)d_in[24];
    const float* cnb = (const float*)d_in[25];
    const float* f1W = (const float*)d_in[26];
    const float* f1b = (const float*)d_in[27];
    const float* f2W = (const float*)d_in[28];
    const float* f2b = (const float*)d_in[29];
    const float* f3W = (const float*)d_in[30];
    const float* f3b = (const float*)d_in[31];
    float* out = (float*)d_out;

    float *x, *hsd, *t1, *y, *m, *h, *sum, *sq, *scale, *shift, *bias2;
    int *deg, *off, *cur, *adj;
    __nv_bfloat16 *athi, *atlo, *rbfhi, *rbflo, *xhi, *xlo, *t1hi, *t1lo,
                  *yhi, *ylo, *f1hi, *f1lo, *f2hi, *f2lo, *wthi, *wtlo;
    cudaGetSymbolAddress((void**)&x,    g_x);
    cudaGetSymbolAddress((void**)&hsd,  g_hsd);
    cudaGetSymbolAddress((void**)&t1,   g_t1);
    cudaGetSymbolAddress((void**)&y,    g_y);
    cudaGetSymbolAddress((void**)&m,    g_m);
    cudaGetSymbolAddress((void**)&h,    g_h);
    cudaGetSymbolAddress((void**)&sum,  g_sum);
    cudaGetSymbolAddress((void**)&sq,   g_sq);
    cudaGetSymbolAddress((void**)&scale, g_scale);
    cudaGetSymbolAddress((void**)&shift, g_shift);
    cudaGetSymbolAddress((void**)&bias2, g_bias2);
    cudaGetSymbolAddress((void**)&deg, g_deg);
    cudaGetSymbolAddress((void**)&off, g_off);
    cudaGetSymbolAddress((void**)&cur, g_cur);
    cudaGetSymbolAddress((void**)&adj, g_adj);
    cudaGetSymbolAddress((void**)&athi, g_athi);
    cudaGetSymbolAddress((void**)&atlo, g_atlo);
    cudaGetSymbolAddress((void**)&rbfhi, g_rbfhi);
    cudaGetSymbolAddress((void**)&rbflo, g_rbflo);
    cudaGetSymbolAddress((void**)&xhi, g_xhi);
    cudaGetSymbolAddress((void**)&xlo, g_xlo);
    cudaGetSymbolAddress((void**)&t1hi, g_t1hi);
    cudaGetSymbolAddress((void**)&t1lo, g_t1lo);
    cudaGetSymbolAddress((void**)&yhi, g_yhi);
    cudaGetSymbolAddress((void**)&ylo, g_ylo);
    cudaGetSymbolAddress((void**)&f1hi, g_f1hi);
    cudaGetSymbolAddress((void**)&f1lo, g_f1lo);
    cudaGetSymbolAddress((void**)&f2hi, g_f2hi);
    cudaGetSymbolAddress((void**)&f2lo, g_f2lo);
    cudaGetSymbolAddress((void**)&wthi, g_wthi);
    cudaGetSymbolAddress((void**)&wtlo, g_wtlo);

    cudaFuncSetAttribute(gemm_tc<false, false>,
                         cudaFuncAttributeMaxDynamicSharedMemorySize, SMEM_TOTAL_TC);
    cudaFuncSetAttribute(gemm_tc<false, true>,
                         cudaFuncAttributeMaxDynamicSharedMemorySize, SMEM_TOTAL_TC);
    cudaFuncSetAttribute(gemm_tc<true, true>,
                         cudaFuncAttributeMaxDynamicSharedMemorySize, SMEM_TOTAL_TC);

    const int TPB = 256;
    auto blocks = [](long long n) { return (int)((n + 255) / 256); };

    // ---- CSR build for dst-gather (once per call; reused by all 4 layers) ----
    zero_int<<<blocks(NN), TPB>>>(deg, NN);
    zero_int<<<blocks(NN), TPB>>>(cur, NN);
    deg_count<<<blocks(EE), TPB>>>(dst, deg);
    scan_offsets<<<1, 1024>>>(deg, off);
    fill_adj<<<blocks(EE), TPB>>>(dst, off, cur, adj);

    // ---- atom embedding: TC (K padded 92->96), fused stats ----
    pad_split<<<blocks((long long)NN * KP96), TPB>>>(atom, athi, atlo, NN, F_ATOM, KP96);
    launch_transpose_split(aW, wthi, wtlo, F_ATOM, HH, KP96);
    launch_gemm<false, true>(athi, atlo, wthi, wtlo, ab, x, nullptr, nullptr,
                             NN, HH, KP96, 0, nullptr, nullptr, nullptr, nullptr, 0,
                             sum, sq);
    finalize_stats<<<1, 512>>>(sum, sq, ag, abeta, scale, shift, HH, 1.f / NN);
    bn_relu_split<<<blocks((long long)NN * HH), TPB>>>(x, (long long)NN * HH, HH,
                                                       scale, shift, xhi, xlo, 1);

    // ---- edge embedding: RBF -> TC e1 (K padded 80->96), fused stats ----
    rbf_split<<<blocks((long long)EE * KP96), TPB>>>(r, rbfhi, rbflo,
                                                     (long long)EE * KP96);
    launch_transpose_split(e1W, wthi, wtlo, BINS, EMB, KP96);
    launch_gemm<false, true>(rbfhi, rbflo, wthi, wtlo, e1b, t1, nullptr, nullptr,
                             EE, EMB, KP96, 0, nullptr, nullptr, nullptr, nullptr, 0,
                             sum, sq);
    finalize_stats<<<1, 512>>>(sum, sq, e1g, e1beta, scale, shift, EMB, 1.f / EE);
    bn_relu_split<<<blocks((long long)EE * EMB), TPB>>>(t1, (long long)EE * EMB, EMB,
                                                        scale, shift, t1hi, t1lo, 0);

    // e2: [E,64] x [64,256] (TC) with fused column stats
    launch_transpose_split(e2W, wthi, wtlo, EMB, HH, EMB);
    launch_gemm<false, true>(t1hi, t1lo, wthi, wtlo, e2b, y, nullptr, nullptr,
                             EE, HH, EMB, 0, nullptr, nullptr, nullptr, nullptr, 0,
                             sum, sq);
    finalize_stats<<<1, 512>>>(sum, sq, e2g, e2beta, scale, shift, HH, 1.f / EE);
    bn_relu_split<<<blocks((long long)EE * HH), TPB>>>(y, (long long)EE * HH, HH,
                                                       scale, shift, yhi, ylo, 0);

    // ---- CGCNN conv layers ----
    for (int l = 0; l < LL; l++) {
        const float* Ws = cWs + (size_t)l * HH * 2 * HH;
        const float* bs = cbs + (size_t)l * 2 * HH;
        const float* Wd = cWd + (size_t)l * HH * 2 * HH;
        const float* bd = cbd + (size_t)l * 2 * HH;
        const float* We = cWe + (size_t)l * HH * 2 * HH;
        const float* be = cbe + (size_t)l * 2 * HH;
        const float* mg = cmg + (size_t)l * 2 * HH;
        const float* mb = cmb + (size_t)l * 2 * HH;
        const float* ng = cng + (size_t)l * HH;
        const float* nb = cnb + (size_t)l * HH;

        // combined hs|hd GEMM: N=1024, Wt = [Ws^T ; Wd^T]
        launch_transpose_split(Ws, wthi, wtlo, HH, 2 * HH, HH);
        launch_transpose_split(Wd, wthi + (size_t)512 * HH, wtlo + (size_t)512 * HH,
                               HH, 2 * HH, HH);
        concat_bias<<<4, 256>>>(bs, bd, bias2);
        launch_gemm<false, false>(xhi, xlo, wthi, wtlo, bias2, hsd, nullptr, nullptr,
                                  NN, 1024, HH, 0);

        // m GEMM with fused gather (hsd[src] + hsd[dst]+512) and fused BN stats
        launch_transpose_split(We, wthi, wtlo, HH, 2 * HH, HH);
        launch_gemm<true, true>(yhi, ylo, wthi, wtlo, be, m, nullptr, nullptr,
                                EE, 2 * HH, HH, 0, src, dst, hsd, hsd + 512, 1024,
                                sum, sq);
        finalize_stats<<<1, 512>>>(sum, sq, mg, mb, scale, shift, 512, 1.f / EE);

        // CSR gather: gate + segment-sum without atomics
        gate_gather<<<NN, 256>>>(m, scale, shift, off, adj, h);

        col_stats<<<1024, TPB>>>(h, (long long)NN * HH, HH, sum, sq);
        finalize_stats<<<1, 512>>>(sum, sq, ng, nb, scale, shift, HH, 1.f / NN);
        node_update<<<blocks((long long)NN * HH), TPB>>>(x, h, scale, shift,
                                                         xhi, xlo, (long long)NN * HH);
    }

    // ---- head (all TC) ----
    launch_transpose_split(f1W, wthi, wtlo, HH, 4 * HH, HH);
    launch_gemm<false, false>(xhi, xlo, wthi, wtlo, f1b, nullptr, f1hi, f1lo,
                              NN, 4 * HH, HH, 1);
    launch_transpose_split(f2W, wthi, wtlo, 4 * HH, 8 * HH, 4 * HH);
    launch_gemm<false, false>(f1hi, f1lo, wthi, wtlo, f2b, nullptr, f2hi, f2lo,
                              NN, 8 * HH, 4 * HH, 1);
    launch_transpose_split(f3W, wthi, wtlo, 8 * HH, FINAL, 8 * HH);
    launch_gemm<false, false>(f2hi, f2lo, wthi, wtlo, f3b, out, nullptr, nullptr,
                              NN, FINAL, 8 * HH, 1);
}

// round 17
// speedup vs baseline: 1.0195x; 1.0195x over previous
#include <cuda_runtime.h>
#include <cuda_bf16.h>
#include <math.h>
#include <stdint.h>

// Problem constants
#define NN 10000
#define EE 160000
#define LL 4
#define F_ATOM 92
#define BINS 80
#define EMB 64
#define HH 256
#define FINAL 10000
#define KP96 96

// ======================= scratch (device globals) ============================
__device__ float g_x  [(size_t)NN * HH];
__device__ float g_hsd[(size_t)NN * 1024];      // [N, hs|hd]
__device__ float g_t1 [(size_t)EE * EMB];
__device__ float g_y  [(size_t)EE * HH];
__device__ float g_m  [(size_t)EE * 2 * HH];
__device__ float g_h  [(size_t)NN * HH];
__device__ float g_sum[1024];                   // zero-init; finalize re-zeroes
__device__ float g_sq [1024];
__device__ float g_scale[512];
__device__ float g_shift[512];
__device__ float g_bias2[1024];
// CSR for dst-gather
__device__ int g_deg[NN];
__device__ int g_off[NN + 1];
__device__ int g_cur[NN];
__device__ int g_adj[EE];
// bf16 hi/lo split buffers
__device__ __nv_bfloat16 g_athi[(size_t)NN * KP96];
__device__ __nv_bfloat16 g_atlo[(size_t)NN * KP96];
__device__ __nv_bfloat16 g_rbfhi[(size_t)EE * KP96];
__device__ __nv_bfloat16 g_rbflo[(size_t)EE * KP96];
__device__ __nv_bfloat16 g_xhi [(size_t)NN * HH];
__device__ __nv_bfloat16 g_xlo [(size_t)NN * HH];
__device__ __nv_bfloat16 g_t1hi[(size_t)EE * EMB];
__device__ __nv_bfloat16 g_t1lo[(size_t)EE * EMB];
__device__ __nv_bfloat16 g_yhi [(size_t)EE * HH];
__device__ __nv_bfloat16 g_ylo [(size_t)EE * HH];
__device__ __nv_bfloat16 g_f1hi[(size_t)NN * 4 * HH];
__device__ __nv_bfloat16 g_f1lo[(size_t)NN * 4 * HH];
__device__ __nv_bfloat16 g_f2hi[(size_t)NN * 8 * HH];
__device__ __nv_bfloat16 g_f2lo[(size_t)NN * 8 * HH];
__device__ __nv_bfloat16 g_wthi[(size_t)FINAL * 2048];
__device__ __nv_bfloat16 g_wtlo[(size_t)FINAL * 2048];

// ======================= math helpers ========================================
__device__ __forceinline__ float softplusf(float x) {
    return fmaxf(x, 0.f) + log1pf(expf(-fabsf(x)));
}
__device__ __forceinline__ float sigmoidf(float x) {
    return 1.f / (1.f + expf(-x));
}

// ======================= mma.sync helpers ====================================
#define LDMATRIX_X4(R, addr) \
    asm volatile("ldmatrix.sync.aligned.m8n8.x4.shared.b16 {%0,%1,%2,%3}, [%4];" \
        : "=r"((R)[0]), "=r"((R)[1]), "=r"((R)[2]), "=r"((R)[3]) : "r"(addr))

#define MMA_BF16(d, a, b0, b1) \
    asm volatile("mma.sync.aligned.m16n8k16.row.col.f32.bf16.bf16.f32 " \
        "{%0,%1,%2,%3}, {%4,%5,%6,%7}, {%8,%9}, {%0,%1,%2,%3};" \
        : "+f"((d)[0]), "+f"((d)[1]), "+f"((d)[2]), "+f"((d)[3]) \
        : "r"((a)[0]), "r"((a)[1]), "r"((a)[2]), "r"((a)[3]), "r"(b0), "r"(b1))

#define CP_ASYNC_16(dst, src, sz) \
    asm volatile("cp.async.cg.shared.global [%0], [%1], 16, %2;" \
        :: "r"(dst), "l"(src), "r"(sz))
#define CP_ASYNC_COMMIT() asm volatile("cp.async.commit_group;" ::: "memory")
#define CP_ASYNC_WAIT0()  asm volatile("cp.async.wait_group 0;" ::: "memory")

// ======================= tensor-core GEMM (mma.sync bf16 split) ==============
// C[M,N2] = (Ahi+Alo)[M,K] x ((Bhi+Blo)[N2,K])^T + bias  (Ah*Bh+Ah*Bl+Al*Bh)
// Template-fused options:
//   GATHER: + ghs[gsrc[row]*gstride] + ghd[gdst[row]*gstride]
//   STATS:  column sum/sumsq atomics (BN batch stats)
// CTA tile 128x128, K-chunk 32, 2-stage cp.async double buffer (R14 config).
// 1-D swizzled raster (RASTER_G=8): B streamed once per group of M-tiles.

#define PITCHB 80             // bytes per smem row (40 bf16) -> conflict-free
#define TILE_BYTES (128 * PITCHB)          // 10240
#define OFF_AH 0
#define OFF_AL (TILE_BYTES)
#define OFF_BH (2 * TILE_BYTES)
#define OFF_BL (3 * TILE_BYTES)
#define STAGE_BYTES (4 * TILE_BYTES)       // 40960
#define SMEM_TOTAL_TC (2 * STAGE_BYTES)    // 81920
#define RASTER_G 8

template<bool GATHER, bool STATS>
__global__ __launch_bounds__(256) void gemm_tc(
    const __nv_bfloat16* __restrict__ Ahi, const __nv_bfloat16* __restrict__ Alo,
    const __nv_bfloat16* __restrict__ Bhi, const __nv_bfloat16* __restrict__ Blo,
    const float* __restrict__ bias,
    float* __restrict__ C,
    __nv_bfloat16* __restrict__ Chi, __nv_bfloat16* __restrict__ Clo,
    int M, int N2, int K, int relu,
    const int* __restrict__ gsrc, const int* __restrict__ gdst,
    const float* __restrict__ ghs, const float* __restrict__ ghd, int gstride,
    float* __restrict__ statSum, float* __restrict__ statSq)
{
    extern __shared__ char sm[];
    const uint32_t sb = (uint32_t)__cvta_generic_to_shared(sm);
    const int tid  = threadIdx.x;
    const int lane = tid & 31;
    const int wid  = tid >> 5;
    const int warp_m = wid & 1;
    const int warp_n = wid >> 1;

    // 1-D swizzled raster (pure indexing; bijective also when Mt % G != 0)
    const int Mt = (M + 127) >> 7;
    const int Nt = (N2 + 127) >> 7;
    const int pid = blockIdx.x;
    const int nig = RASTER_G * Nt;
    const int group_id = pid / nig;
    const int first_m = group_id * RASTER_G;
    int gsz = Mt - first_m; if (gsz > RASTER_G) gsz = RASTER_G;
    const int rem = pid % nig;
    const int m0 = (first_m + rem % gsz) << 7;
    const int n0 = (rem / gsz) << 7;

    float acc[4][4][4];
    #pragma unroll
    for (int i = 0; i < 4; i++)
        #pragma unroll
        for (int j = 0; j < 4; j++)
            #pragma unroll
            for (int k = 0; k < 4; k++) acc[i][j][k] = 0.f;

    const int nch = K >> 5;
    const int r0_ = tid >> 2;
    const int r1_ = (tid + 256) >> 2;
    const int c0_ = (tid & 3) * 16;

    auto issue_chunk = [&](int ch) {
        const long long kb = (long long)ch << 5;
        const uint32_t sbase = sb + (ch & 1) * STAGE_BYTES;
        #pragma unroll
        for (int half = 0; half < 2; half++) {
            const int row = half ? r1_ : r0_;
            const int cb = c0_;
            {
                int gr = m0 + row;
                int ok = (gr < M) ? 16 : 0;
                long long go = ((long long)gr * K + kb) * 2 + cb;
                CP_ASYNC_16(sbase + OFF_AH + row * PITCHB + cb, (const char*)Ahi + go, ok);
                CP_ASYNC_16(sbase + OFF_AL + row * PITCHB + cb, (const char*)Alo + go, ok);
            }
            {
                int gr = n0 + row;
                int ok = (gr < N2) ? 16 : 0;
                long long go = ((long long)gr * K + kb) * 2 + cb;
                CP_ASYNC_16(sbase + OFF_BH + row * PITCHB + cb, (const char*)Bhi + go, ok);
                CP_ASYNC_16(sbase + OFF_BL + row * PITCHB + cb, (const char*)Blo + go, ok);
            }
        }
        CP_ASYNC_COMMIT();
    };

    const int a_row = warp_m * 64 + (lane & 15);
    const int a_col = (lane >> 4) << 3;
    const int b_row = warp_n * 32 + ((lane >> 4) << 3) + (lane & 7);
    const int b_col = (lane >> 3 & 1) << 3;

    issue_chunk(0);

    for (int ch = 0; ch < nch; ch++) {
        CP_ASYNC_WAIT0();
        __syncthreads();
        if (ch + 1 < nch) issue_chunk(ch + 1);

        const uint32_t sbase = sb + (ch & 1) * STAGE_BYTES;
        #pragma unroll
        for (int ks = 0; ks < 32; ks += 16) {
            uint32_t af[4][4], bh[2][4], bl[2][4];
            #pragma unroll
            for (int mt = 0; mt < 4; mt++)
                LDMATRIX_X4(af[mt], sbase + OFF_AH + (a_row + mt * 16) * PITCHB + (a_col + ks) * 2);
            #pragma unroll
            for (int pp = 0; pp < 2; pp++)
                LDMATRIX_X4(bh[pp], sbase + OFF_BH + (b_row + pp * 16) * PITCHB + (b_col + ks) * 2);
            #pragma unroll
            for (int mt = 0; mt < 4; mt++)
                #pragma unroll
                for (int nt = 0; nt < 4; nt++)
                    MMA_BF16(acc[mt][nt], af[mt],
                             bh[nt >> 1][(nt & 1) * 2], bh[nt >> 1][(nt & 1) * 2 + 1]);
            #pragma unroll
            for (int pp = 0; pp < 2; pp++)
                LDMATRIX_X4(bl[pp], sbase + OFF_BL + (b_row + pp * 16) * PITCHB + (b_col + ks) * 2);
            #pragma unroll
            for (int mt = 0; mt < 4; mt++)
                #pragma unroll
                for (int nt = 0; nt < 4; nt++)
                    MMA_BF16(acc[mt][nt], af[mt],
                             bl[nt >> 1][(nt & 1) * 2], bl[nt >> 1][(nt & 1) * 2 + 1]);
            #pragma unroll
            for (int mt = 0; mt < 4; mt++)
                LDMATRIX_X4(af[mt], sbase + OFF_AL + (a_row + mt * 16) * PITCHB + (a_col + ks) * 2);
            #pragma unroll
            for (int mt = 0; mt < 4; mt++)
                #pragma unroll
                for (int nt = 0; nt < 4; nt++)
                    MMA_BF16(acc[mt][nt], af[mt],
                             bh[nt >> 1][(nt & 1) * 2], bh[nt >> 1][(nt & 1) * 2 + 1]);
        }
        __syncthreads();
    }

    // epilogue
    const int er = m0 + warp_m * 64 + (lane >> 2);
    const int ec = n0 + warp_n * 32 + (lane & 3) * 2;

    float bvals[8];
    #pragma unroll
    for (int nt = 0; nt < 4; nt++)
        #pragma unroll
        for (int d = 0; d < 2; d++) {
            int gc = ec + nt * 8 + d;
            bvals[nt * 2 + d] = (gc < N2) ? bias[gc] : 0.f;
        }

    float csum[8], csq[8];
    if (STATS) {
        #pragma unroll
        for (int j = 0; j < 8; j++) { csum[j] = 0.f; csq[j] = 0.f; }
    }

    #pragma unroll
    for (int mt = 0; mt < 4; mt++) {
        #pragma unroll
        for (int half = 0; half < 2; half++) {
            int gr = er + mt * 16 + half * 8;
            if (gr >= M) continue;
            long long rb = (long long)gr * N2;
            const float* hsrow = nullptr;
            const float* hdrow = nullptr;
            if (GATHER) {
                hsrow = ghs + (long long)gsrc[gr] * gstride;
                hdrow = ghd + (long long)gdst[gr] * gstride;
            }
            #pragma unroll
            for (int nt = 0; nt < 4; nt++) {
                #pragma unroll
                for (int d = 0; d < 2; d++) {
                    int gc = ec + nt * 8 + d;
                    if (gc >= N2) continue;
                    float v = acc[mt][nt][half * 2 + d] + bvals[nt * 2 + d];
                    if (GATHER) v += hsrow[gc] + hdrow[gc];
                    if (relu) v = fmaxf(v, 0.f);
                    if (C) C[rb + gc] = v;
                    if (Chi) {
                        __nv_bfloat16 hb = __float2bfloat16(v);
                        Chi[rb + gc] = hb;
                        Clo[rb + gc] = __float2bfloat16(v - __bfloat162float(hb));
                    }
                    if (STATS) {
                        csum[nt * 2 + d] += v;
                        csq[nt * 2 + d]  += v * v;
                    }
                }
            }
        }
    }

    if (STATS) {
        #pragma unroll
        for (int j = 0; j < 8; j++) {
            float s = csum[j], q = csq[j];
            s += __shfl_xor_sync(0xFFFFFFFFu, s, 4);
            q += __shfl_xor_sync(0xFFFFFFFFu, q, 4);
            s += __shfl_xor_sync(0xFFFFFFFFu, s, 8);
            q += __shfl_xor_sync(0xFFFFFFFFu, q, 8);
            s += __shfl_xor_sync(0xFFFFFFFFu, s, 16);
            q += __shfl_xor_sync(0xFFFFFFFFu, q, 16);
            if (lane < 4) {
                int gc = n0 + warp_n * 32 + (j >> 1) * 8 + lane * 2 + (j & 1);
                if (gc < N2) {
                    atomicAdd(&statSum[gc], s);
                    atomicAdd(&statSq[gc], q);
                }
            }
        }
    }
}

// ======================= conversion kernels ==================================
__global__ void transpose_split(const float* __restrict__ W,
                                __nv_bfloat16* __restrict__ hi,
                                __nv_bfloat16* __restrict__ lo,
                                int K, int N, int Kpad) {
    __shared__ float tile[32][33];
    int kb = blockIdx.y * 32, nb = blockIdx.x * 32;
    #pragma unroll
    for (int i = 0; i < 32; i += 8) {
        int kk = kb + threadIdx.y + i;
        int nn = nb + threadIdx.x;
        tile[threadIdx.y + i][threadIdx.x] =
            (kk < K && nn < N) ? W[(long long)kk * N + nn] : 0.f;
    }
    __syncthreads();
    #pragma unroll
    for (int i = 0; i < 32; i += 8) {
        int nn = nb + threadIdx.y + i;
        int kk = kb + threadIdx.x;
        if (nn < N && kk < Kpad) {
            float v = tile[threadIdx.x][threadIdx.y + i];
            __nv_bfloat16 h = __float2bfloat16(v);
            hi[(long long)nn * Kpad + kk] = h;
            lo[(long long)nn * Kpad + kk] = __float2bfloat16(v - __bfloat162float(h));
        }
    }
}

__global__ void pad_split(const float* __restrict__ in,
                          __nv_bfloat16* __restrict__ hi,
                          __nv_bfloat16* __restrict__ lo,
                          long long rows, int Ks, int Kp) {
    long long i = (long long)blockIdx.x * blockDim.x + threadIdx.x;
    if (i >= rows * Kp) return;
    long long r = i / Kp;
    int c = (int)(i % Kp);
    float v = (c < Ks) ? in[r * Ks + c] : 0.f;
    __nv_bfloat16 h = __float2bfloat16(v);
    hi[i] = h;
    lo[i] = __float2bfloat16(v - __bfloat162float(h));
}

// ======================= CSR build kernels ===================================
__global__ void zero_int(int* __restrict__ p, int n) {
    int i = blockIdx.x * blockDim.x + threadIdx.x;
    if (i < n) p[i] = 0;
}

__global__ void deg_count(const int* __restrict__ dst, int* __restrict__ deg) {
    int e = blockIdx.x * blockDim.x + threadIdx.x;
    if (e < EE) atomicAdd(&deg[dst[e]], 1);
}

// single block of 1024 threads, each handles 10 consecutive nodes
__global__ void scan_offsets(const int* __restrict__ deg, int* __restrict__ off) {
    __shared__ int s[1024];
    int t = threadIdx.x;
    int base = t * 10;
    int loc[10];
    int sum = 0;
    #pragma unroll
    for (int i = 0; i < 10; i++) {
        int idx = base + i;
        int v = (idx < NN) ? deg[idx] : 0;
        loc[i] = sum;
        sum += v;
    }
    s[t] = sum;
    __syncthreads();
    for (int d = 1; d < 1024; d <<= 1) {
        int v = (t >= d) ? s[t - d] : 0;
        __syncthreads();
        s[t] += v;
        __syncthreads();
    }
    int excl = (t == 0) ? 0 : s[t - 1];
    #pragma unroll
    for (int i = 0; i < 10; i++) {
        int idx = base + i;
        if (idx < NN) off[idx] = excl + loc[i];
    }
    if (t == 1023) off[NN] = s[1023];
}

__global__ void fill_adj(const int* __restrict__ dst, const int* __restrict__ off,
                         int* __restrict__ cur, int* __restrict__ adj) {
    int e = blockIdx.x * blockDim.x + threadIdx.x;
    if (e >= EE) return;
    int n = dst[e];
    int p = atomicAdd(&cur[n], 1);
    adj[off[n] + p] = e;
}

// ======================= elementwise / stats kernels =========================
__global__ void concat_bias(const float* __restrict__ a, const float* __restrict__ b,
                            float* __restrict__ o) {
    int i = blockIdx.x * blockDim.x + threadIdx.x;
    if (i < 512) o[i] = a[i];
    else if (i < 1024) o[i] = b[i - 512];
}

__global__ void rbf_split(const float* __restrict__ r,
                          __nv_bfloat16* __restrict__ hi,
                          __nv_bfloat16* __restrict__ lo,
                          long long n) {
    long long i = (long long)blockIdx.x * blockDim.x + threadIdx.x;
    if (i >= n) return;
    int e = (int)(i / KP96);
    int b = (int)(i % KP96);
    float v = 0.f;
    if (b < BINS) {
        float rx = r[e * 3 + 0], ry = r[e * 3 + 1], rz = r[e * 3 + 2];
        float d = sqrtf(rx * rx + ry * ry + rz * rz);
        float ctr = (8.0f / 79.0f) * (float)b;
        float t = d - ctr;
        v = expf(-9.875f * t * t);
    }
    __nv_bfloat16 h = __float2bfloat16(v);
    hi[i] = h;
    lo[i] = __float2bfloat16(v - __bfloat162float(h));
}

// computes scale/shift AND re-zeroes sum/sq for the next use
__global__ void finalize_stats(float* __restrict__ sum, float* __restrict__ sq,
                               const float* __restrict__ gamma, const float* __restrict__ beta,
                               float* __restrict__ scale, float* __restrict__ shift,
                               int N, float invM) {
    int c = blockIdx.x * blockDim.x + threadIdx.x;
    if (c >= N) return;
    float mean = sum[c] * invM;
    float var  = sq[c] * invM - mean * mean;
    float inv  = rsqrtf(var + 1e-5f);
    float s    = gamma[c] * inv;
    scale[c] = s;
    shift[c] = beta[c] - mean * s;
    sum[c] = 0.f;
    sq[c]  = 0.f;
}

__global__ void bn_relu_split(float* __restrict__ X, long long n, int N,
                              const float* __restrict__ scale,
                              const float* __restrict__ shift,
                              __nv_bfloat16* __restrict__ hi,
                              __nv_bfloat16* __restrict__ lo,
                              int writeback) {
    long long i = (long long)blockIdx.x * blockDim.x + threadIdx.x;
    if (i >= n) return;
    int c = (int)(i % N);
    float v = fmaxf(fmaf(X[i], scale[c], shift[c]), 0.f);
    if (writeback) X[i] = v;
    __nv_bfloat16 h = __float2bfloat16(v);
    hi[i] = h;
    lo[i] = __float2bfloat16(v - __bfloat162float(h));
}

// CSR gather: block = node, thread = channel. No atomics on h; h written once.
// Fused: column sum/sumsq of h accumulated via global atomics (256 addresses).
__global__ __launch_bounds__(256) void gate_gather(
    const float* __restrict__ m,
    const float* __restrict__ scale, const float* __restrict__ shift,
    const int* __restrict__ off, const int* __restrict__ adj,
    float* __restrict__ h,
    float* __restrict__ statSum, float* __restrict__ statSq)
{
    int n = blockIdx.x;
    int c = threadIdx.x;
    float sa = scale[c], fa = shift[c];
    float sb = scale[256 + c], fb = shift[256 + c];
    float acc = 0.f;
    int i0 = off[n], i1 = off[n + 1];
    for (int i = i0; i < i1; i++) {
        int e = adj[i];
        long long base = (long long)e * 512;
        float a = fmaf(m[base + c],       sa, fa);
        float b = fmaf(m[base + 256 + c], sb, fb);
        acc += sigmoidf(a) * softplusf(b);
    }
    h[(long long)n * 256 + c] = acc;
    atomicAdd(&statSum[c], acc);
    atomicAdd(&statSq[c], acc * acc);
}

__global__ void node_update(float* __restrict__ x, const float* __restrict__ h,
                            const float* __restrict__ scale, const float* __restrict__ shift,
                            __nv_bfloat16* __restrict__ xhi, __nv_bfloat16* __restrict__ xlo,
                            long long n) {
    long long i = (long long)blockIdx.x * blockDim.x + threadIdx.x;
    if (i >= n) return;
    int c = (int)(i & 255);
    float hb = fmaf(h[i], scale[c], shift[c]);
    float v = softplusf(x[i] + hb);
    x[i] = v;
    __nv_bfloat16 hh = __float2bfloat16(v);
    xhi[i] = hh;
    xlo[i] = __float2bfloat16(v - __bfloat162float(hh));
}

// ======================= host orchestration ==================================
template<bool GATHER, bool STATS>
static inline void launch_gemm(const __nv_bfloat16* Ahi, const __nv_bfloat16* Alo,
                               const __nv_bfloat16* Bhi, const __nv_bfloat16* Blo,
                               const float* bias, float* C,
                               __nv_bfloat16* Chi, __nv_bfloat16* Clo,
                               int M, int N, int K, int relu,
                               const int* gsrc = nullptr, const int* gdst = nullptr,
                               const float* ghs = nullptr, const float* ghd = nullptr,
                               int gstride = 0,
                               float* ssum = nullptr, float* ssq = nullptr) {
    int Mt = (M + 127) / 128, Nt = (N + 127) / 128;
    gemm_tc<GATHER, STATS><<<Mt * Nt, 256, SMEM_TOTAL_TC>>>(
        Ahi, Alo, Bhi, Blo, bias, C, Chi, Clo, M, N, K, relu,
        gsrc, gdst, ghs, ghd, gstride, ssum, ssq);
}

static inline void launch_transpose_split(const float* W, __nv_bfloat16* hi,
                                          __nv_bfloat16* lo, int K, int N, int Kpad) {
    dim3 grid((N + 31) / 32, (Kpad + 31) / 32);
    transpose_split<<<grid, dim3(32, 8)>>>(W, hi, lo, K, N, Kpad);
}

extern "C" void kernel_launch(void* const* d_in, const int* in_sizes, int n_in,
                              void* d_out, int out_size) {
    const float* atom = (const float*)d_in[0];
    const float* r    = (const float*)d_in[1];
    const int*   src  = (const int*)d_in[2];
    const int*   dst  = (const int*)d_in[3];
    const float* aW = (const float*)d_in[4];
    const float* ab = (const float*)d_in[5];
    const float* ag = (const float*)d_in[6];
    const float* abeta = (const float*)d_in[7];
    const float* e1W = (const float*)d_in[8];
    const float* e1b = (const float*)d_in[9];
    const float* e1g = (const float*)d_in[10];
    const float* e1beta = (const float*)d_in[11];
    const float* e2W = (const float*)d_in[12];
    const float* e2b = (const float*)d_in[13];
    const float* e2g = (const float*)d_in[14];
    const float* e2beta = (const float*)d_in[15];
    const float* cWs = (const float*)d_in[16];
    const float* cbs = (const float*)d_in[17];
    const float* cWd = (const float*)d_in[18];
    const float* cbd = (const float*)d_in[19];
    const float* cWe = (const float*)d_in[20];
    const float* cbe = (const float*)d_in[21];
    const float* cmg = (const float*)d_in[22];
    const float* cmb = (const float*)d_in[23];
    const float* cng = (const float*)d_in[24];
    const float* cnb = (const float*)d_in[25];
    const float* f1W = (const float*)d_in[26];
    const float* f1b = (const float*)d_in[27];
    const float* f2W = (const float*)d_in[28];
    const float* f2b = (const float*)d_in[29];
    const float* f3W = (const float*)d_in[30];
    const float* f3b = (const float*)d_in[31];
    float* out = (float*)d_out;

    float *x, *hsd, *t1, *y, *m, *h, *sum, *sq, *scale, *shift, *bias2;
    int *deg, *off, *cur, *adj;
    __nv_bfloat16 *athi, *atlo, *rbfhi, *rbflo, *xhi, *xlo, *t1hi, *t1lo,
                  *yhi, *ylo, *f1hi, *f1lo, *f2hi, *f2lo, *wthi, *wtlo;
    cudaGetSymbolAddress((void**)&x,    g_x);
    cudaGetSymbolAddress((void**)&hsd,  g_hsd);
    cudaGetSymbolAddress((void**)&t1,   g_t1);
    cudaGetSymbolAddress((void**)&y,    g_y);
    cudaGetSymbolAddress((void**)&m,    g_m);
    cudaGetSymbolAddress((void**)&h,    g_h);
    cudaGetSymbolAddress((void**)&sum,  g_sum);
    cudaGetSymbolAddress((void**)&sq,   g_sq);
    cudaGetSymbolAddress((void**)&scale, g_scale);
    cudaGetSymbolAddress((void**)&shift, g_shift);
    cudaGetSymbolAddress((void**)&bias2, g_bias2);
    cudaGetSymbolAddress((void**)&deg, g_deg);
    cudaGetSymbolAddress((void**)&off, g_off);
    cudaGetSymbolAddress((void**)&cur, g_cur);
    cudaGetSymbolAddress((void**)&adj, g_adj);
    cudaGetSymbolAddress((void**)&athi, g_athi);
    cudaGetSymbolAddress((void**)&atlo, g_atlo);
    cudaGetSymbolAddress((void**)&rbfhi, g_rbfhi);
    cudaGetSymbolAddress((void**)&rbflo, g_rbflo);
    cudaGetSymbolAddress((void**)&xhi, g_xhi);
    cudaGetSymbolAddress((void**)&xlo, g_xlo);
    cudaGetSymbolAddress((void**)&t1hi, g_t1hi);
    cudaGetSymbolAddress((void**)&t1lo, g_t1lo);
    cudaGetSymbolAddress((void**)&yhi, g_yhi);
    cudaGetSymbolAddress((void**)&ylo, g_ylo);
    cudaGetSymbolAddress((void**)&f1hi, g_f1hi);
    cudaGetSymbolAddress((void**)&f1lo, g_f1lo);
    cudaGetSymbolAddress((void**)&f2hi, g_f2hi);
    cudaGetSymbolAddress((void**)&f2lo, g_f2lo);
    cudaGetSymbolAddress((void**)&wthi, g_wthi);
    cudaGetSymbolAddress((void**)&wtlo, g_wtlo);

    cudaFuncSetAttribute(gemm_tc<false, false>,
                         cudaFuncAttributeMaxDynamicSharedMemorySize, SMEM_TOTAL_TC);
    cudaFuncSetAttribute(gemm_tc<false, true>,
                         cudaFuncAttributeMaxDynamicSharedMemorySize, SMEM_TOTAL_TC);
    cudaFuncSetAttribute(gemm_tc<true, true>,
                         cudaFuncAttributeMaxDynamicSharedMemorySize, SMEM_TOTAL_TC);

    const int TPB = 256;
    auto blocks = [](long long n) { return (int)((n + 255) / 256); };

    // ---- CSR build for dst-gather (once per call; reused by all 4 layers) ----
    zero_int<<<blocks(NN), TPB>>>(deg, NN);
    zero_int<<<blocks(NN), TPB>>>(cur, NN);
    deg_count<<<blocks(EE), TPB>>>(dst, deg);
    scan_offsets<<<1, 1024>>>(deg, off);
    fill_adj<<<blocks(EE), TPB>>>(dst, off, cur, adj);

    // ---- atom embedding: TC (K padded 92->96), fused stats ----
    pad_split<<<blocks((long long)NN * KP96), TPB>>>(atom, athi, atlo, NN, F_ATOM, KP96);
    launch_transpose_split(aW, wthi, wtlo, F_ATOM, HH, KP96);
    launch_gemm<false, true>(athi, atlo, wthi, wtlo, ab, x, nullptr, nullptr,
                             NN, HH, KP96, 0, nullptr, nullptr, nullptr, nullptr, 0,
                             sum, sq);
    finalize_stats<<<1, 512>>>(sum, sq, ag, abeta, scale, shift, HH, 1.f / NN);
    bn_relu_split<<<blocks((long long)NN * HH), TPB>>>(x, (long long)NN * HH, HH,
                                                       scale, shift, xhi, xlo, 1);

    // ---- edge embedding: RBF -> TC e1 (K padded 80->96), fused stats ----
    rbf_split<<<blocks((long long)EE * KP96), TPB>>>(r, rbfhi, rbflo,
                                                     (long long)EE * KP96);
    launch_transpose_split(e1W, wthi, wtlo, BINS, EMB, KP96);
    launch_gemm<false, true>(rbfhi, rbflo, wthi, wtlo, e1b, t1, nullptr, nullptr,
                             EE, EMB, KP96, 0, nullptr, nullptr, nullptr, nullptr, 0,
                             sum, sq);
    finalize_stats<<<1, 512>>>(sum, sq, e1g, e1beta, scale, shift, EMB, 1.f / EE);
    bn_relu_split<<<blocks((long long)EE * EMB), TPB>>>(t1, (long long)EE * EMB, EMB,
                                                        scale, shift, t1hi, t1lo, 0);

    // e2: [E,64] x [64,256] (TC) with fused column stats
    launch_transpose_split(e2W, wthi, wtlo, EMB, HH, EMB);
    launch_gemm<false, true>(t1hi, t1lo, wthi, wtlo, e2b, y, nullptr, nullptr,
                             EE, HH, EMB, 0, nullptr, nullptr, nullptr, nullptr, 0,
                             sum, sq);
    finalize_stats<<<1, 512>>>(sum, sq, e2g, e2beta, scale, shift, HH, 1.f / EE);
    bn_relu_split<<<blocks((long long)EE * HH), TPB>>>(y, (long long)EE * HH, HH,
                                                       scale, shift, yhi, ylo, 0);

    // ---- CGCNN conv layers ----
    for (int l = 0; l < LL; l++) {
        const float* Ws = cWs + (size_t)l * HH * 2 * HH;
        const float* bs = cbs + (size_t)l * 2 * HH;
        const float* Wd = cWd + (size_t)l * HH * 2 * HH;
        const float* bd = cbd + (size_t)l * 2 * HH;
        const float* We = cWe + (size_t)l * HH * 2 * HH;
        const float* be = cbe + (size_t)l * 2 * HH;
        const float* mg = cmg + (size_t)l * 2 * HH;
        const float* mb = cmb + (size_t)l * 2 * HH;
        const float* ng = cng + (size_t)l * HH;
        const float* nb = cnb + (size_t)l * HH;

        // combined hs|hd GEMM: N=1024, Wt = [Ws^T ; Wd^T]
        launch_transpose_split(Ws, wthi, wtlo, HH, 2 * HH, HH);
        launch_transpose_split(Wd, wthi + (size_t)512 * HH, wtlo + (size_t)512 * HH,
                               HH, 2 * HH, HH);
        concat_bias<<<4, 256>>>(bs, bd, bias2);
        launch_gemm<false, false>(xhi, xlo, wthi, wtlo, bias2, hsd, nullptr, nullptr,
                                  NN, 1024, HH, 0);

        // m GEMM with fused gather (hsd[src] + hsd[dst]+512) and fused BN stats
        launch_transpose_split(We, wthi, wtlo, HH, 2 * HH, HH);
        launch_gemm<true, true>(yhi, ylo, wthi, wtlo, be, m, nullptr, nullptr,
                                EE, 2 * HH, HH, 0, src, dst, hsd, hsd + 512, 1024,
                                sum, sq);
        finalize_stats<<<1, 512>>>(sum, sq, mg, mb, scale, shift, 512, 1.f / EE);

        // CSR gather: gate + segment-sum without atomics; h-stats fused
        gate_gather<<<NN, 256>>>(m, scale, shift, off, adj, h, sum, sq);

        finalize_stats<<<1, 512>>>(sum, sq, ng, nb, scale, shift, HH, 1.f / NN);
        node_update<<<blocks((long long)NN * HH), TPB>>>(x, h, scale, shift,
                                                         xhi, xlo, (long long)NN * HH);
    }

    // ---- head (all TC) ----
    launch_transpose_split(f1W, wthi, wtlo, HH, 4 * HH, HH);
    launch_gemm<false, false>(xhi, xlo, wthi, wtlo, f1b, nullptr, f1hi, f1lo,
                              NN, 4 * HH, HH, 1);
    launch_transpose_split(f2W, wthi, wtlo, 4 * HH, 8 * HH, 4 * HH);
    launch_gemm<false, false>(f1hi, f1lo, wthi, wtlo, f2b, nullptr, f2hi, f2lo,
                              NN, 8 * HH, 4 * HH, 1);
    launch_transpose_split(f3W, wthi, wtlo, 8 * HH, FINAL, 8 * HH);
    launch_gemm<false, false>(f2hi, f2lo, wthi, wtlo, f3b, out, nullptr, nullptr,
                              NN, FINAL, 8 * HH, 1);
}